// round 4
// baseline (speedup 1.0000x reference)
#include <cuda_runtime.h>

// out[n][c] = in[n][c] + glob[batch[n]][c]
// N = 1,000,000, C = 128, B = 8, fp32.  ~1.03 GB streamed.
//
// R4: persistent grid-stride CTAs (no wave transitions), ILP=4 per iteration,
//     contiguous per-block slabs for DRAM locality, 32-bit indexing.

static constexpr int C_VEC   = 128 / 4;  // 32 float4 per row
static constexpr int UNROLL  = 4;
static constexpr int THREADS = 256;
static constexpr int GRID    = 148 * 8;  // persistent: one wave fills the chip

__global__ __launch_bounds__(THREADS)
void sparse_global_broadcast_kernel(const float4* __restrict__ in,
                                    const float4* __restrict__ glob,
                                    const int*    __restrict__ bidx,
                                    float4*       __restrict__ out,
                                    unsigned n_vec) {
    const unsigned chunk  = THREADS * UNROLL;                 // 1024 float4 / iter
    const unsigned stride = chunk * GRID;                     // full-chip step

    for (unsigned base = blockIdx.x * chunk + threadIdx.x;
         base < n_vec; base += stride) {

        float4 a[UNROLL];
        int    b[UNROLL];
        bool   ok[UNROLL];

        // Front-batch independent loads: 4x LDG.128 + 4x LDG.32.
        #pragma unroll
        for (int u = 0; u < UNROLL; u++) {
            unsigned i = base + u * THREADS;
            ok[u] = i < n_vec;
            if (ok[u]) {
                a[u] = __ldcs(&in[i]);           // evict-first streaming load
                b[u] = __ldg(&bidx[i >> 5]);     // warp-uniform, cached
            }
        }

        #pragma unroll
        for (int u = 0; u < UNROLL; u++) {
            if (ok[u]) {
                unsigned i = base + u * THREADS;
                unsigned lane = i & 31;
                float4 g = __ldg(&glob[(unsigned)b[u] * C_VEC + lane]);  // 4 KB, L1-hit
                float4 r;
                r.x = a[u].x + g.x;
                r.y = a[u].y + g.y;
                r.z = a[u].z + g.z;
                r.w = a[u].w + g.w;
                __stcs(&out[i], r);              // streaming store
            }
        }
    }
}

extern "C" void kernel_launch(void* const* d_in, const int* in_sizes, int n_in,
                              void* d_out, int out_size) {
    const float4* in   = (const float4*)d_in[0];   // input_features        [N, C]
    const float4* glob = (const float4*)d_in[1];   // input_features_global [B, C]
    const int*    bidx = (const int*)d_in[2];      // batch_indices         [N]

    float4* out = (float4*)d_out;

    unsigned n_vec = (unsigned)((long long)in_sizes[0] / 4);   // N*C/4 = 32M

    sparse_global_broadcast_kernel<<<GRID, THREADS>>>(in, glob, bidx, out, n_vec);
}

// round 5
// speedup vs baseline: 1.0744x; 1.0744x over previous
#include <cuda_runtime.h>

// out[n][c] = in[n][c] + glob[batch[n]][c]
// N = 1,000,000, C = 128, B = 8, fp32.  ~1.03 GB streamed -> ~144 us @ 6.8 TB/s achieved.
//
// R5: flat grid (block-level pipelining beats persistent loops for streaming),
//     ILP=4 front-batched LDG.128, unguarded fast path, 32-bit indexing.

static constexpr int C_VEC   = 128 / 4;  // 32 float4 per row
static constexpr int UNROLL  = 4;
static constexpr int THREADS = 256;

template <bool GUARD>
__global__ __launch_bounds__(THREADS)
void sparse_global_broadcast_kernel(const float4* __restrict__ in,
                                    const float4* __restrict__ glob,
                                    const int*    __restrict__ bidx,
                                    float4*       __restrict__ out,
                                    unsigned n_vec) {
    unsigned base = blockIdx.x * (THREADS * UNROLL) + threadIdx.x;

    float4 a[UNROLL];
    int    b[UNROLL];

    // Front-batch all independent loads: 4x LDG.128 (stream) + 4x LDG.32 (bidx).
    #pragma unroll
    for (int u = 0; u < UNROLL; u++) {
        unsigned i = base + u * THREADS;
        if (!GUARD || i < n_vec) {
            a[u] = __ldcs(&in[i]);            // evict-first streaming load
            b[u] = __ldg(&bidx[i >> 5]);      // warp-uniform row index, cached
        }
    }

    #pragma unroll
    for (int u = 0; u < UNROLL; u++) {
        unsigned i = base + u * THREADS;
        if (!GUARD || i < n_vec) {
            unsigned lane = i & 31;
            float4 g = __ldg(&glob[(unsigned)b[u] * C_VEC + lane]);  // 4 KB, L1-hit
            float4 r;
            r.x = a[u].x + g.x;
            r.y = a[u].y + g.y;
            r.z = a[u].z + g.z;
            r.w = a[u].w + g.w;
            __stcs(&out[i], r);               // streaming store
        }
    }
}

extern "C" void kernel_launch(void* const* d_in, const int* in_sizes, int n_in,
                              void* d_out, int out_size) {
    const float4* in   = (const float4*)d_in[0];   // input_features        [N, C]
    const float4* glob = (const float4*)d_in[1];   // input_features_global [B, C]
    const int*    bidx = (const int*)d_in[2];      // batch_indices         [N]

    float4* out = (float4*)d_out;

    unsigned n_vec = (unsigned)((long long)in_sizes[0] / 4);   // N*C/4 = 32M
    unsigned per_block = THREADS * UNROLL;                      // 1024
    unsigned blocks = (n_vec + per_block - 1) / per_block;

    if (n_vec % per_block == 0) {
        sparse_global_broadcast_kernel<false><<<blocks, THREADS>>>(in, glob, bidx, out, n_vec);
    } else {
        sparse_global_broadcast_kernel<true><<<blocks, THREADS>>>(in, glob, bidx, out, n_vec);
    }
}

// round 6
// speedup vs baseline: 1.0755x; 1.0011x over previous
#include <cuda_runtime.h>

// out[n][c] = in[n][c] + glob[batch[n]][c]
// N = 1,000,000, C = 128, B = 8, fp32.  ~1.03 GB streamed, ~7 TB/s achieved at pins.
//
// R6: flat grid, 512-thread blocks (halved block-boundary drain overhead),
//     ILP=4 front-batched LDG.128, unguarded fast path, 32-bit indexing.

static constexpr int C_VEC   = 128 / 4;  // 32 float4 per row
static constexpr int UNROLL  = 4;
static constexpr int THREADS = 512;

template <bool GUARD>
__global__ __launch_bounds__(THREADS)
void sparse_global_broadcast_kernel(const float4* __restrict__ in,
                                    const float4* __restrict__ glob,
                                    const int*    __restrict__ bidx,
                                    float4*       __restrict__ out,
                                    unsigned n_vec) {
    unsigned base = blockIdx.x * (THREADS * UNROLL) + threadIdx.x;

    float4 a[UNROLL];
    int    b[UNROLL];

    // Front-batch all independent loads: 4x LDG.128 (stream) + 4x LDG.32 (bidx).
    #pragma unroll
    for (int u = 0; u < UNROLL; u++) {
        unsigned i = base + u * THREADS;
        if (!GUARD || i < n_vec) {
            a[u] = __ldcs(&in[i]);            // evict-first streaming load
            b[u] = __ldg(&bidx[i >> 5]);      // warp-uniform row index, cached
        }
    }

    #pragma unroll
    for (int u = 0; u < UNROLL; u++) {
        unsigned i = base + u * THREADS;
        if (!GUARD || i < n_vec) {
            unsigned lane = i & 31;
            float4 g = __ldg(&glob[(unsigned)b[u] * C_VEC + lane]);  // 4 KB, L1-hit
            float4 r;
            r.x = a[u].x + g.x;
            r.y = a[u].y + g.y;
            r.z = a[u].z + g.z;
            r.w = a[u].w + g.w;
            __stcs(&out[i], r);               // streaming store
        }
    }
}

extern "C" void kernel_launch(void* const* d_in, const int* in_sizes, int n_in,
                              void* d_out, int out_size) {
    const float4* in   = (const float4*)d_in[0];   // input_features        [N, C]
    const float4* glob = (const float4*)d_in[1];   // input_features_global [B, C]
    const int*    bidx = (const int*)d_in[2];      // batch_indices         [N]

    float4* out = (float4*)d_out;

    unsigned n_vec = (unsigned)((long long)in_sizes[0] / 4);   // N*C/4 = 32M
    unsigned per_block = THREADS * UNROLL;                      // 2048
    unsigned blocks = (n_vec + per_block - 1) / per_block;

    if (n_vec % per_block == 0) {
        sparse_global_broadcast_kernel<false><<<blocks, THREADS>>>(in, glob, bidx, out, n_vec);
    } else {
        sparse_global_broadcast_kernel<true><<<blocks, THREADS>>>(in, glob, bidx, out, n_vec);
    }
}